// round 5
// baseline (speedup 1.0000x reference)
#include <cuda_runtime.h>
#include <cuda_bf16.h>

#define TT 2048
#define BB 256
#define VV 90
#define PP 89
#define IGNORE_IDX 999
#define EPS_F 1e-28f
#define LN2_F 0.69314718055994530942f
#define LOG2E_F 1.4426950408889634074f

#define NBLOCKS 2048
#define WARPS_PER_BLOCK 8
#define THREADS 256
#define PAIRS_PER_WARP 32
// 2048*8*32 == 524288 == TT*BB

// smem transpose buffer: 36-float row stride -> conflict-free STS.32 (banks
// (4k+lane)%32 distinct) and conflict-free LDS.128 (lane l covers banks
// 4l..4l+3 within each 8-lane phase).
#define SROW 36

__device__ double g_partials[NBLOCKS];
__device__ unsigned int g_counter = 0;

__device__ __forceinline__ float warp_sum(float v) {
    #pragma unroll
    for (int off = 16; off > 0; off >>= 1)
        v += __shfl_xor_sync(0xFFFFFFFFu, v, off);
    return v;
}

__global__ __launch_bounds__(THREADS)
void trans_inv_loss_kernel(const float* __restrict__ first_scores,
                           const float* __restrict__ pattern_scores,
                           const int*   __restrict__ first_targs,
                           const float* __restrict__ pattern_targs,
                           const int*   __restrict__ lengths,
                           float* __restrict__ out) {
    __shared__ float sbuf[WARPS_PER_BLOCK][32][SROW];

    const int lane = threadIdx.x & 31;
    const int wib  = threadIdx.x >> 5;
    const int w    = blockIdx.x * WARPS_PER_BLOCK + wib;
    const int base = w * PAIRS_PER_WARP;          // 32 consecutive pairs, same t
    const int t    = base >> 8;
    const int b0   = base & (BB - 1);

    // Coalesced: this lane's own pair's target + liveness
    const int targ_my = first_targs[base + lane];           // 0..89 or 999
    const int live_my = (t < lengths[b0 + lane]) ? 1 : 0;
    const int packed_my = targ_my | (live_my << 10);

    float bce_log2 = 0.0f;      // lane-local across all pairs/channels

    const float* row  = first_scores   + (size_t)base * VV;
    const float* prow = pattern_scores + (size_t)base * PP;
    const float* trow = pattern_targs  + (size_t)base * PP;

    // ---------------- Phase 1: per-pair partials, no reductions ----------------
    #pragma unroll 4
    for (int k = 0; k < PAIRS_PER_WARP;
         k++, row += VV, prow += PP, trow += PP) {
        const int packed = __shfl_sync(0xFFFFFFFFu, packed_my, k);
        const int targ = packed & 1023;
        const int live = packed >> 10;

        // CE partial: each lane's share of sum(2^(x*lg2e)); rows 8B-aligned
        const float2* row2 = (const float2*)row;
        float2 lo = row2[lane];
        float s = exp2f(lo.x * LOG2E_F) + exp2f(lo.y * LOG2E_F);
        if (lane < 13) {
            float2 hi = row2[32 + lane];
            s += exp2f(hi.x * LOG2E_F) + exp2f(hi.y * LOG2E_F);
        }
        sbuf[wib][k][lane] = s;                    // transpose write

        // BCE over prefix kc < 89 - targ; kmax warp-uniform -> no divergence
        if (live) {
            const int kmax = PP - targ;
            if (lane < kmax) {
                float p  = prow[lane];
                float y  = trow[lane];
                float lp = __log2f(p + EPS_F);
                float lq = __log2f(1.0f - p);
                bce_log2 -= fmaf(y, lp - lq, lq);
            }
            if (kmax > 32) {
                const int k1 = lane + 32;
                if (k1 < kmax) {
                    float p  = prow[k1];
                    float y  = trow[k1];
                    float lp = __log2f(p + EPS_F);
                    float lq = __log2f(1.0f - p);
                    bce_log2 -= fmaf(y, lp - lq, lq);
                }
                if (kmax > 64) {
                    const int k2 = lane + 64;
                    if (k2 < kmax) {
                        float p  = prow[k2];
                        float y  = trow[k2];
                        float lp = __log2f(p + EPS_F);
                        float lq = __log2f(1.0f - p);
                        bce_log2 -= fmaf(y, lp - lq, lq);
                    }
                }
            }
        }
    }

    __syncwarp();

    // ---------------- Phase 2: lane l finishes pair (base + l) ----------------
    // Sum 32 partials of my pair: 8x LDS.128, conflict-free, tree-summed
    const float4* myrow = (const float4*)sbuf[wib][lane];
    float4 a0 = myrow[0], a1 = myrow[1], a2 = myrow[2], a3 = myrow[3];
    float4 a4 = myrow[4], a5 = myrow[5], a6 = myrow[6], a7 = myrow[7];
    float s0 = (a0.x + a0.y) + (a0.z + a0.w);
    float s1 = (a1.x + a1.y) + (a1.z + a1.w);
    float s2 = (a2.x + a2.y) + (a2.z + a2.w);
    float s3 = (a3.x + a3.y) + (a3.z + a3.w);
    float s4 = (a4.x + a4.y) + (a4.z + a4.w);
    float s5 = (a5.x + a5.y) + (a5.z + a5.w);
    float s6 = (a6.x + a6.y) + (a6.z + a6.w);
    float s7 = (a7.x + a7.y) + (a7.z + a7.w);
    float s_mine = ((s0 + s1) + (s2 + s3)) + ((s4 + s5) + (s6 + s7));

    float ce_log2 = 0.0f, xt = 0.0f;
    if (targ_my != IGNORE_IDX) {
        int tc = targ_my < 0 ? 0 : (targ_my > VV - 1 ? VV - 1 : targ_my);
        ce_log2 = __log2f(s_mine);
        xt = first_scores[(size_t)(base + lane) * VV + tc];   // L1/L2 hit
    }

    // Single butterfly per warp over the combined lane value
    float v = fmaf(LN2_F, ce_log2 + bce_log2, -xt);
    float warp_loss = warp_sum(v);

    __shared__ double sdata[WARPS_PER_BLOCK];
    __shared__ int is_last;
    if (lane == 0)
        sdata[wib] = (double)warp_loss;
    __syncthreads();

    if (threadIdx.x == 0) {
        double blk = 0.0;
        #pragma unroll
        for (int i = 0; i < WARPS_PER_BLOCK; i++) blk += sdata[i];
        g_partials[blockIdx.x] = blk;
        __threadfence();
        unsigned int ticket = atomicAdd(&g_counter, 1u);
        is_last = (ticket == (unsigned)(NBLOCKS - 1)) ? 1 : 0;
    }
    __syncthreads();

    if (is_last) {
        __shared__ double red[THREADS];
        double a = 0.0;
        #pragma unroll
        for (int i = threadIdx.x; i < NBLOCKS; i += THREADS)
            a += __ldcg(&g_partials[i]);          // fixed order, deterministic
        red[threadIdx.x] = a;
        __syncthreads();
        #pragma unroll
        for (int off = THREADS / 2; off > 0; off >>= 1) {
            if (threadIdx.x < off) red[threadIdx.x] += red[threadIdx.x + off];
            __syncthreads();
        }
        if (threadIdx.x == 0) {
            out[0] = (float)(red[0] / (double)BB);
            g_counter = 0;                        // reset for next replay
        }
    }
}

extern "C" void kernel_launch(void* const* d_in, const int* in_sizes, int n_in,
                              void* d_out, int out_size) {
    const float* first_scores   = (const float*)d_in[0];
    const float* pattern_scores = (const float*)d_in[1];
    const int*   first_targs    = (const int*)  d_in[2];
    const float* pattern_targs  = (const float*)d_in[3];
    const int*   lengths        = (const int*)  d_in[4];
    float* out = (float*)d_out;

    trans_inv_loss_kernel<<<NBLOCKS, THREADS>>>(
        first_scores, pattern_scores, first_targs, pattern_targs, lengths, out);
}

// round 6
// speedup vs baseline: 1.6525x; 1.6525x over previous
#include <cuda_runtime.h>
#include <cuda_bf16.h>

#define TT 2048
#define BB 256
#define VV 90
#define PP 89
#define IGNORE_IDX 999
#define EPS_F 1e-28f
#define LN2_F 0.69314718055994530942f
#define LOG2E_F 1.4426950408889634074f

#define NBLOCKS 2048
#define WARPS_PER_BLOCK 8
#define THREADS 256
#define PAIRS_PER_WARP 32
// 2048*8*32 == 524288 == TT*BB

__device__ double g_partials[NBLOCKS];
__device__ unsigned int g_counter = 0;

__device__ __forceinline__ float warp_sum(float v) {
    #pragma unroll
    for (int off = 16; off > 0; off >>= 1)
        v += __shfl_xor_sync(0xFFFFFFFFu, v, off);
    return v;
}

__global__ __launch_bounds__(THREADS)
void trans_inv_loss_kernel(const float* __restrict__ first_scores,
                           const float* __restrict__ pattern_scores,
                           const int*   __restrict__ first_targs,
                           const float* __restrict__ pattern_targs,
                           const int*   __restrict__ lengths,
                           float* __restrict__ out) {
    const int lane = threadIdx.x & 31;
    const int wib  = threadIdx.x >> 5;
    const int w    = blockIdx.x * WARPS_PER_BLOCK + wib;
    const int base = w * PAIRS_PER_WARP;          // 32 consecutive pairs, same t
    const int t    = base >> 8;
    const int b0   = base & (BB - 1);
    const int half = lane >> 4;                   // 0: even pair, 1: odd pair
    const int hl   = lane & 15;                   // lane within half-warp

    // Coalesced: targets + liveness for the warp's 32 pairs, packed per lane
    const int targ_my = first_targs[base + lane];           // 0..89 or 999
    const int live_my = (t < lengths[b0 + lane]) ? 1 : 0;
    const int packed_my = targ_my | (live_my << 10);

    float ce_log2_acc = 0.0f;   // only lanes 0 and 16 accumulate
    float xt_acc      = 0.0f;   // only lanes 0 and 16 accumulate
    float bce_log2    = 0.0f;   // all lanes

    const float* rowp = first_scores   + (size_t)base * VV;
    const float* prow = pattern_scores + (size_t)base * PP;
    const float* trow = pattern_targs  + (size_t)base * PP;

    #pragma unroll 2
    for (int k = 0; k < PAIRS_PER_WARP;
         k += 2, rowp += 2 * VV, prow += 2 * PP, trow += 2 * PP) {

        // ---- CE for pairs k (lanes 0-15) and k+1 (lanes 16-31) ----
        const float* crow = rowp + half * VV;
        const float2* c2 = (const float2*)crow;        // 8B-aligned rows
        float2 v0 = c2[hl];                            // floats 2hl,2hl+1
        float2 v1 = c2[hl + 16];                       // floats 32..63
        float s = exp2f(v0.x * LOG2E_F) + exp2f(v0.y * LOG2E_F)
                + exp2f(v1.x * LOG2E_F) + exp2f(v1.y * LOG2E_F);
        if (hl < 13) {                                 // floats 64..89
            float2 v2 = c2[hl + 32];
            s += exp2f(v2.x * LOG2E_F) + exp2f(v2.y * LOG2E_F);
        }
        // 4-step butterfly within each half-warp (never crosses 16-boundary)
        #pragma unroll
        for (int off = 8; off > 0; off >>= 1)
            s += __shfl_xor_sync(0xFFFFFFFFu, s, off);

        const int pk_ce = __shfl_sync(0xFFFFFFFFu, packed_my, k + half);
        const int targ_ce = pk_ce & 1023;
        if (targ_ce != IGNORE_IDX && hl == 0) {
            int tc = targ_ce > VV - 1 ? VV - 1 : targ_ce;
            ce_log2_acc += __log2f(s);
            xt_acc      += crow[tc];                   // L1/L2 hit
        }

        // ---- BCE for pair k, full warp; warp-uniform skip branches ----
        const int pk0 = __shfl_sync(0xFFFFFFFFu, packed_my, k);
        if (pk0 >> 10) {
            const int kmax = PP - (pk0 & 1023);
            if (lane < kmax) {
                float p  = prow[lane];
                float y  = trow[lane];
                float lp = __log2f(p + EPS_F);
                float lq = __log2f(1.0f - p);
                bce_log2 -= fmaf(y, lp - lq, lq);
            }
            if (kmax > 32) {
                const int k1 = lane + 32;
                if (k1 < kmax) {
                    float p  = prow[k1];
                    float y  = trow[k1];
                    float lp = __log2f(p + EPS_F);
                    float lq = __log2f(1.0f - p);
                    bce_log2 -= fmaf(y, lp - lq, lq);
                }
                if (kmax > 64) {
                    const int k2 = lane + 64;
                    if (k2 < kmax) {
                        float p  = prow[k2];
                        float y  = trow[k2];
                        float lp = __log2f(p + EPS_F);
                        float lq = __log2f(1.0f - p);
                        bce_log2 -= fmaf(y, lp - lq, lq);
                    }
                }
            }
        }

        // ---- BCE for pair k+1 ----
        const int pk1 = __shfl_sync(0xFFFFFFFFu, packed_my, k + 1);
        if (pk1 >> 10) {
            const int kmax = PP - (pk1 & 1023);
            const float* prow1 = prow + PP;
            const float* trow1 = trow + PP;
            if (lane < kmax) {
                float p  = prow1[lane];
                float y  = trow1[lane];
                float lp = __log2f(p + EPS_F);
                float lq = __log2f(1.0f - p);
                bce_log2 -= fmaf(y, lp - lq, lq);
            }
            if (kmax > 32) {
                const int k1 = lane + 32;
                if (k1 < kmax) {
                    float p  = prow1[k1];
                    float y  = trow1[k1];
                    float lp = __log2f(p + EPS_F);
                    float lq = __log2f(1.0f - p);
                    bce_log2 -= fmaf(y, lp - lq, lq);
                }
                if (kmax > 64) {
                    const int k2 = lane + 64;
                    if (k2 < kmax) {
                        float p  = prow1[k2];
                        float y  = trow1[k2];
                        float lp = __log2f(p + EPS_F);
                        float lq = __log2f(1.0f - p);
                        bce_log2 -= fmaf(y, lp - lq, lq);
                    }
                }
            }
        }
    }

    // Combine: loss = ln2*(ce_log2 + bce_log2) - xt, summed over warp
    float v = fmaf(LN2_F, ce_log2_acc + bce_log2, -xt_acc);
    float warp_loss = warp_sum(v);

    __shared__ double sdata[WARPS_PER_BLOCK];
    __shared__ int is_last;
    if (lane == 0)
        sdata[wib] = (double)warp_loss;
    __syncthreads();

    if (threadIdx.x == 0) {
        double blk = 0.0;
        #pragma unroll
        for (int i = 0; i < WARPS_PER_BLOCK; i++) blk += sdata[i];
        g_partials[blockIdx.x] = blk;
        __threadfence();
        unsigned int ticket = atomicAdd(&g_counter, 1u);
        is_last = (ticket == (unsigned)(NBLOCKS - 1)) ? 1 : 0;
    }
    __syncthreads();

    if (is_last) {
        __shared__ double red[THREADS];
        double a = 0.0;
        #pragma unroll
        for (int i = threadIdx.x; i < NBLOCKS; i += THREADS)
            a += __ldcg(&g_partials[i]);          // fixed order, deterministic
        red[threadIdx.x] = a;
        __syncthreads();
        #pragma unroll
        for (int off = THREADS / 2; off > 0; off >>= 1) {
            if (threadIdx.x < off) red[threadIdx.x] += red[threadIdx.x + off];
            __syncthreads();
        }
        if (threadIdx.x == 0) {
            out[0] = (float)(red[0] / (double)BB);
            g_counter = 0;                        // reset for next replay
        }
    }
}

extern "C" void kernel_launch(void* const* d_in, const int* in_sizes, int n_in,
                              void* d_out, int out_size) {
    const float* first_scores   = (const float*)d_in[0];
    const float* pattern_scores = (const float*)d_in[1];
    const int*   first_targs    = (const int*)  d_in[2];
    const float* pattern_targs  = (const float*)d_in[3];
    const int*   lengths        = (const int*)  d_in[4];
    float* out = (float*)d_out;

    trans_inv_loss_kernel<<<NBLOCKS, THREADS>>>(
        first_scores, pattern_scores, first_targs, pattern_targs, lengths, out);
}